// round 3
// baseline (speedup 1.0000x reference)
#include <cuda_runtime.h>
#include <cuda_bf16.h>
#include <math.h>

#define N_NODES 40000
#define E_EDGES 1280000
#define S_DIM 64
#define V_DIM 16
#define R_DIM 32

// Per-node attention projections (Pa includes ba1), computed by proj_kernel.
__device__ float g_Pa[N_NODES * S_DIM];
__device__ float g_Pb[N_NODES * S_DIM];

// ---------------------------------------------------------------------------
// Kernel 1: initialize output = [scalars ; vectors]
// ---------------------------------------------------------------------------
__global__ void init_out_kernel(const float* __restrict__ scalars,
                                const float* __restrict__ vectors,
                                float* __restrict__ out) {
    const int NS4 = (N_NODES * S_DIM) / 4;          // 640000
    const int NV4 = (N_NODES * V_DIM * 3) / 4;      // 480000
    int i = blockIdx.x * blockDim.x + threadIdx.x;
    if (i < NS4) {
        reinterpret_cast<float4*>(out)[i] =
            reinterpret_cast<const float4*>(scalars)[i];
    } else if (i < NS4 + NV4) {
        reinterpret_cast<float4*>(out)[i] =
            reinterpret_cast<const float4*>(vectors)[i - NS4];
    }
}

// ---------------------------------------------------------------------------
// Kernel 2: per-node projections Pa = ba1 + scalars @ Wa1[0:64],
//                                 Pb =      scalars @ Wa1[64:128]
// ---------------------------------------------------------------------------
#define PROJ_NB 16
__global__ __launch_bounds__(256) void proj_kernel(
    const float* __restrict__ scalars,
    const float* __restrict__ Wa1,
    const float* __restrict__ ba1) {
    __shared__ __align__(16) float sW[128 * 64];       // Wa1 rows 0..127 (32 KB)
    __shared__ __align__(16) float sS[PROJ_NB * 64];   // 16 scalar rows  (4 KB)

    const int tid = threadIdx.x;
    const int n0 = blockIdx.x * PROJ_NB;

    for (int i = tid; i < 128 * 64; i += 256) sW[i] = Wa1[i];
    for (int i = tid; i < PROJ_NB * 64; i += 256) sS[i] = scalars[n0 * 64 + i];
    __syncthreads();

    const int j = tid & 63;
    const int grp = tid >> 6;

    const float b = __ldg(&ba1[j]);
    for (int nn = grp; nn < PROJ_NB; nn += 4) {
        float pa = b;
        float pb = 0.0f;
#pragma unroll 8
        for (int k = 0; k < 64; k++) {
            float s = sS[nn * 64 + k];
            pa = fmaf(s, sW[k * 64 + j], pa);
            pb = fmaf(s, sW[(64 + k) * 64 + j], pb);
        }
        g_Pa[(n0 + nn) * 64 + j] = pa;
        g_Pb[(n0 + nn) * 64 + j] = pb;
    }
}

// ---------------------------------------------------------------------------
// Kernel 3: edge kernel. 8 warps/block, 4 edges per warp per tile,
// grid-stride over 40000 tiles of 32 edges.
// ---------------------------------------------------------------------------
__device__ __forceinline__ float silu_f(float x) {
    return x / (1.0f + __expf(-x));
}
__device__ __forceinline__ float dot4(float4 a, float4 b) {
    return fmaf(a.x, b.x, fmaf(a.y, b.y, fmaf(a.z, b.z, a.w * b.w)));
}

__global__ __launch_bounds__(256) void edge_kernel(
    const float* __restrict__ edge_vec,
    const int* __restrict__ ei,          // int32! JAX default disables x64.
    const float* __restrict__ scalars,
    const float* __restrict__ vectors,
    const float* __restrict__ W1,
    const float* __restrict__ b1,
    const float* __restrict__ W2,
    const float* __restrict__ b2,
    const float* __restrict__ Wa1,
    const float* __restrict__ Wa2,
    const float* __restrict__ ba2,
    float* __restrict__ out) {

    __shared__ __align__(16) float sW1[8 * 32 * 4];     // [g][j][i] = W1[(4g+i)*32 + j]
    __shared__ __align__(16) float sW2[8 * 3 * 32 * 4]; // [g][c][j][i] = W2[(4g+i)*96+32c+j]
    __shared__ __align__(16) float sWr[8 * 2 * 32 * 4]; // [g][c][j][i] = Wa1[(128+4g+i)*64+32c+j]
    __shared__ __align__(16) float sB1[32];
    __shared__ __align__(16) float sB2[96];
    __shared__ __align__(16) float sWa2[64];
    __shared__ __align__(16) float sRbf[8][4][32];
    __shared__ __align__(16) float sH1[8][4][32];

    const int tid = threadIdx.x;
    for (int idx = tid; idx < 1024; idx += 256) {
        int g = idx >> 7, r = idx & 127, j = r >> 2, i = r & 3;
        sW1[idx] = W1[(4 * g + i) * 32 + j];
    }
    for (int idx = tid; idx < 3072; idx += 256) {
        int g = idx / 384, r = idx % 384;
        int c = r >> 7, r2 = r & 127, j = r2 >> 2, i = r2 & 3;
        sW2[idx] = W2[(4 * g + i) * 96 + 32 * c + j];
    }
    for (int idx = tid; idx < 2048; idx += 256) {
        int g = idx >> 8, r = idx & 255;
        int c = r >> 7, r2 = r & 127, j = r2 >> 2, i = r2 & 3;
        sWr[idx] = Wa1[(128 + 4 * g + i) * 64 + 32 * c + j];
    }
    if (tid < 32) sB1[tid] = b1[tid];
    if (tid < 96) sB2[tid] = b2[tid];
    if (tid < 64) sWa2[tid] = Wa2[tid];
    __syncthreads();

    const int warp = tid >> 5;
    const int lane = tid & 31;
    const float ba2v = __ldg(&ba2[0]);
    float* __restrict__ outS = out;
    float* __restrict__ outV = out + N_NODES * S_DIM;

    const int NTILES = E_EDGES / 32;   // 40000

    for (int tile = blockIdx.x; tile < NTILES; tile += gridDim.x) {
        const int e0 = tile * 32 + warp * 4;

        __syncwarp();   // protect sRbf/sH1 reuse across tile iterations

        int src[4], dst[4];
        float ux[4], uy[4], uz[4];
#pragma unroll
        for (int t = 0; t < 4; t++) {
            const int e = e0 + t;
            float x = __ldg(&edge_vec[3 * e + 0]);
            float y = __ldg(&edge_vec[3 * e + 1]);
            float z = __ldg(&edge_vec[3 * e + 2]);
            float d = sqrtf(fmaf(x, x, fmaf(y, y, z * z)));
            float ds = fmaxf(d, 1e-8f);
            float iv = 1.0f / ds;
            float ct = (d < 10.0f) ? 0.5f * (cospif(d * 0.1f) + 1.0f) : 0.0f;
            ux[t] = x * iv; uy[t] = y * iv; uz[t] = z * iv;
            float arg = d * 0.1f * (float)(lane + 1);
            sRbf[warp][t][lane] = sinpif(arg) * iv * ct;
            src[t] = __ldg(&ei[e]);
            dst[t] = __ldg(&ei[E_EDGES + e]);
        }
        __syncwarp();

        // ---- h1 = silu(rbf @ W1 + b1) ----
        float acc[4];
        {
            float bb = sB1[lane];
#pragma unroll
            for (int t = 0; t < 4; t++) acc[t] = bb;
        }
#pragma unroll
        for (int g = 0; g < 8; g++) {
            float4 w = *reinterpret_cast<const float4*>(&sW1[g * 128 + lane * 4]);
#pragma unroll
            for (int t = 0; t < 4; t++) {
                float4 r = *reinterpret_cast<const float4*>(&sRbf[warp][t][g * 4]);
                acc[t] += dot4(w, r);
            }
        }
#pragma unroll
        for (int t = 0; t < 4; t++) sH1[warp][t][lane] = silu_f(acc[t]);
        __syncwarp();

        // ---- filters and attention hidden ----
        float f0[4], f1[4], f2[4], a0[4], a1[4];
        {
            float bb0 = sB2[lane], bb1 = sB2[lane + 32], bb2 = sB2[lane + 64];
#pragma unroll
            for (int t = 0; t < 4; t++) {
                f0[t] = bb0; f1[t] = bb1; f2[t] = bb2;
                a0[t] = g_Pa[dst[t] * 64 + lane] + g_Pb[src[t] * 64 + lane];
                a1[t] = g_Pa[dst[t] * 64 + 32 + lane] + g_Pb[src[t] * 64 + 32 + lane];
            }
        }
#pragma unroll
        for (int g = 0; g < 8; g++) {
            float4 w20 = *reinterpret_cast<const float4*>(&sW2[g * 384 + 0 * 128 + lane * 4]);
            float4 w21 = *reinterpret_cast<const float4*>(&sW2[g * 384 + 1 * 128 + lane * 4]);
            float4 w22 = *reinterpret_cast<const float4*>(&sW2[g * 384 + 2 * 128 + lane * 4]);
            float4 wr0 = *reinterpret_cast<const float4*>(&sWr[g * 256 + 0 * 128 + lane * 4]);
            float4 wr1 = *reinterpret_cast<const float4*>(&sWr[g * 256 + 1 * 128 + lane * 4]);
#pragma unroll
            for (int t = 0; t < 4; t++) {
                float4 h = *reinterpret_cast<const float4*>(&sH1[warp][t][g * 4]);
                float4 r = *reinterpret_cast<const float4*>(&sRbf[warp][t][g * 4]);
                f0[t] += dot4(w20, h);
                f1[t] += dot4(w21, h);
                f2[t] += dot4(w22, h);
                a0[t] += dot4(wr0, r);
                a1[t] += dot4(wr1, r);
            }
        }

        // ---- att = sigmoid(silu(h) @ Wa2 + ba2) ----
        float att[4];
        {
            float wlo = sWa2[lane], whi = sWa2[lane + 32];
#pragma unroll
            for (int t = 0; t < 4; t++) {
                float p = fmaf(silu_f(a0[t]), wlo, silu_f(a1[t]) * whi);
                p += __shfl_xor_sync(0xffffffffu, p, 16);
                p += __shfl_xor_sync(0xffffffffu, p, 8);
                p += __shfl_xor_sync(0xffffffffu, p, 4);
                p += __shfl_xor_sync(0xffffffffu, p, 2);
                p += __shfl_xor_sync(0xffffffffu, p, 1);
                att[t] = 1.0f / (1.0f + __expf(-(p + ba2v)));
            }
        }

        // ---- messages + scatter-add ----
#pragma unroll
        for (int t = 0; t < 4; t++) {
            const float* srow = scalars + src[t] * 64;
            const float a = att[t];
            float m0 = a * __ldg(&srow[lane]) * f0[t];
            float m1 = a * __ldg(&srow[32 + lane]) * f1[t];
            atomicAdd(&outS[dst[t] * 64 + lane], m0);
            atomicAdd(&outS[dst[t] * 64 + 32 + lane], m1);

            const float* vrow = vectors + src[t] * 48;
#pragma unroll
            for (int rr = 0; rr < 2; rr++) {
                int idx = rr * 32 + lane;
                int ic = idx < 48 ? idx : 47;
                int v = ic / 3;
                int c = ic - v * 3;
                float vf = __shfl_sync(0xffffffffu, f2[t], v);
                float vg = __shfl_sync(0xffffffffu, f2[t], v + 16);
                float shc = (c == 0) ? uy[t] : ((c == 1) ? uz[t] : ux[t]);
                if (idx < 48) {
                    float m = a * fmaf(__ldg(&vrow[idx]), vf, vg * shc);
                    atomicAdd(&outV[dst[t] * 48 + idx], m);
                }
            }
        }
    }
}

// ---------------------------------------------------------------------------
extern "C" void kernel_launch(void* const* d_in, const int* in_sizes, int n_in,
                              void* d_out, int out_size) {
    const float* scalars = (const float*)d_in[0];
    const float* vectors = (const float*)d_in[1];
    const float* edge_vec = (const float*)d_in[2];
    const float* W1 = (const float*)d_in[3];
    const float* b1 = (const float*)d_in[4];
    const float* W2 = (const float*)d_in[5];
    const float* b2 = (const float*)d_in[6];
    const float* Wa1 = (const float*)d_in[7];
    const float* ba1 = (const float*)d_in[8];
    const float* Wa2 = (const float*)d_in[9];
    const float* ba2 = (const float*)d_in[10];
    const int* ei = (const int*)d_in[11];
    float* out = (float*)d_out;

    const int TOT4 = (N_NODES * S_DIM + N_NODES * V_DIM * 3) / 4;  // 1,120,000
    init_out_kernel<<<(TOT4 + 255) / 256, 256>>>(scalars, vectors, out);
    proj_kernel<<<N_NODES / 16, 256>>>(scalars, Wa1, ba1);
    edge_kernel<<<1184, 256>>>(edge_vec, ei, scalars, vectors,
                               W1, b1, W2, b2, Wa1, Wa2, ba2, out);
}